// round 1
// baseline (speedup 1.0000x reference)
#include <cuda_runtime.h>
#include <math.h>

#define DIM 64
#define TM 64
#define TN 64

// Scratch for precomputed squared norms (no dynamic allocation allowed).
__device__ float g_x2[8192];
__device__ float g_w2[65536];

// ---------------------------------------------------------------------------
// x2[b] = sum_d x[b,d]^2      (x is [B, 64] row-major, rows contiguous)
// ---------------------------------------------------------------------------
__global__ void x2_kernel(const float* __restrict__ x, int B) {
    int row = blockIdx.x * blockDim.x + threadIdx.x;
    if (row >= B) return;
    const float4* xr = reinterpret_cast<const float4*>(x + (long)row * DIM);
    float s = 0.0f;
#pragma unroll
    for (int i = 0; i < DIM / 4; i++) {
        float4 v = xr[i];
        s += v.x * v.x + v.y * v.y + v.z * v.z + v.w * v.w;
    }
    g_x2[row] = s;
}

// ---------------------------------------------------------------------------
// w2[j] = sum_d w[d,j]^2      (w is [64, K] row-major; column walk, coalesced
// across adjacent threads)
// ---------------------------------------------------------------------------
__global__ void w2_kernel(const float* __restrict__ w, int K) {
    int j = blockIdx.x * blockDim.x + threadIdx.x;
    if (j >= K) return;
    float s = 0.0f;
#pragma unroll
    for (int d = 0; d < DIM; d++) {
        float v = w[(long)d * K + j];
        s += v * v;
    }
    g_w2[j] = s;
}

// ---------------------------------------------------------------------------
// Main fused kernel: 64x64 output tile per block, 256 threads, 4x4 micro-tile.
// Entire D=64 fits in SMEM -> single load phase, then 64 FMA iterations.
//   out[b,j] = sqrt(max(x2[b] + w2[j] - 2 * dot(x[b,:], w[:,j]), 1e-12))
// ---------------------------------------------------------------------------
__global__ __launch_bounds__(256) void dist_kernel(
    const float* __restrict__ x, const float* __restrict__ w,
    float* __restrict__ out, int B, int K)
{
    __shared__ float xT[DIM][TM];  // [k][row]  (transposed for LDS.128)
    __shared__ float wt[DIM][TN];  // [k][col]

    const int b0 = blockIdx.y * TM;
    const int j0 = blockIdx.x * TN;
    const int tid = threadIdx.x;

    // ---- load x tile (64 rows x 64 k), transpose into xT ----
    {
        int r = tid >> 2;        // 0..63 : tile row
        int q = tid & 3;         // 0..3  : which 16-k quarter
        const float4* src =
            reinterpret_cast<const float4*>(x + (long)(b0 + r) * DIM + q * 16);
#pragma unroll
        for (int i = 0; i < 4; i++) {
            float4 v = src[i];
            int k = q * 16 + i * 4;
            xT[k + 0][r] = v.x;
            xT[k + 1][r] = v.y;
            xT[k + 2][r] = v.z;
            xT[k + 3][r] = v.w;
        }
    }

    // ---- load w tile: wt[k][c] = w[k*K + j0 + c], guarded for the tail ----
    {
        int k = tid >> 2;        // 0..63
        int q = tid & 3;         // 0..3
        const float* wrow = w + (long)k * K;
#pragma unroll
        for (int i = 0; i < 4; i++) {
            int c = q * 16 + i * 4;
            int j = j0 + c;
            float4 v;
            if (j + 4 <= K) {
                v = *reinterpret_cast<const float4*>(wrow + j);
            } else {
                v.x = (j + 0 < K) ? wrow[j + 0] : 0.0f;
                v.y = (j + 1 < K) ? wrow[j + 1] : 0.0f;
                v.z = (j + 2 < K) ? wrow[j + 2] : 0.0f;
                v.w = (j + 3 < K) ? wrow[j + 3] : 0.0f;
            }
            wt[k][c + 0] = v.x;
            wt[k][c + 1] = v.y;
            wt[k][c + 2] = v.z;
            wt[k][c + 3] = v.w;
        }
    }

    __syncthreads();

    const int tx = tid & 15;   // col group 0..15
    const int ty = tid >> 4;   // row group 0..15

    float acc[4][4];
#pragma unroll
    for (int i = 0; i < 4; i++)
#pragma unroll
        for (int j = 0; j < 4; j++) acc[i][j] = 0.0f;

#pragma unroll
    for (int k = 0; k < DIM; k++) {
        float4 a = *reinterpret_cast<const float4*>(&xT[k][ty * 4]);
        float4 b = *reinterpret_cast<const float4*>(&wt[k][tx * 4]);
        acc[0][0] += a.x * b.x; acc[0][1] += a.x * b.y;
        acc[0][2] += a.x * b.z; acc[0][3] += a.x * b.w;
        acc[1][0] += a.y * b.x; acc[1][1] += a.y * b.y;
        acc[1][2] += a.y * b.z; acc[1][3] += a.y * b.w;
        acc[2][0] += a.z * b.x; acc[2][1] += a.z * b.y;
        acc[2][2] += a.z * b.z; acc[2][3] += a.z * b.w;
        acc[3][0] += a.w * b.x; acc[3][1] += a.w * b.y;
        acc[3][2] += a.w * b.z; acc[3][3] += a.w * b.w;
    }

    // ---- epilogue: sqrt(max(x2 + w2 - 2*dot, eps)) ----
    float x2v[4], w2v[4];
#pragma unroll
    for (int i = 0; i < 4; i++) x2v[i] = g_x2[b0 + ty * 4 + i];
#pragma unroll
    for (int j = 0; j < 4; j++) {
        int jj = j0 + tx * 4 + j;
        w2v[j] = (jj < K) ? g_w2[jj] : 0.0f;
    }

#pragma unroll
    for (int i = 0; i < 4; i++) {
        long row = b0 + ty * 4 + i;
        int col = j0 + tx * 4;
        float r0 = sqrtf(fmaxf(x2v[i] + w2v[0] - 2.0f * acc[i][0], 1e-12f));
        float r1 = sqrtf(fmaxf(x2v[i] + w2v[1] - 2.0f * acc[i][1], 1e-12f));
        float r2 = sqrtf(fmaxf(x2v[i] + w2v[2] - 2.0f * acc[i][2], 1e-12f));
        float r3 = sqrtf(fmaxf(x2v[i] + w2v[3] - 2.0f * acc[i][3], 1e-12f));
        if (col + 4 <= K) {
            float4 v = make_float4(r0, r1, r2, r3);
            *reinterpret_cast<float4*>(out + row * K + col) = v;
        } else {
            if (col + 0 < K) out[row * K + col + 0] = r0;
            if (col + 1 < K) out[row * K + col + 1] = r1;
            if (col + 2 < K) out[row * K + col + 2] = r2;
            if (col + 3 < K) out[row * K + col + 3] = r3;
        }
    }
}

// ---------------------------------------------------------------------------
// Launch
// ---------------------------------------------------------------------------
extern "C" void kernel_launch(void* const* d_in, const int* in_sizes, int n_in,
                              void* d_out, int out_size) {
    const float* x = (const float*)d_in[0];       // [B, 64]
    const float* w = (const float*)d_in[1];       // [64, K]
    float* out = (float*)d_out;                   // [B, K]

    int B = in_sizes[0] / DIM;
    int K = in_sizes[1] / DIM;

    x2_kernel<<<(B + 255) / 256, 256>>>(x, B);
    w2_kernel<<<(K + 255) / 256, 256>>>(w, K);

    dim3 grid((K + TN - 1) / TN, (B + TM - 1) / TM);
    dist_kernel<<<grid, 256>>>(x, w, out, B, K);
}

// round 3
// speedup vs baseline: 2.5499x; 2.5499x over previous
#include <cuda_runtime.h>
#include <math.h>
#include <stdint.h>

#define DIM 64
#define TM 128
#define TN 128

// Scratch for precomputed squared norms (no dynamic allocation allowed).
__device__ float g_x2[8192];
__device__ float g_w2[65536];

// ---------------------------------------------------------------------------
// Precompute squared norms (exact fp32)
// ---------------------------------------------------------------------------
__global__ void x2_kernel(const float* __restrict__ x, int B) {
    int row = blockIdx.x * blockDim.x + threadIdx.x;
    if (row >= B) return;
    const float4* xr = reinterpret_cast<const float4*>(x + (long)row * DIM);
    float s = 0.0f;
#pragma unroll
    for (int i = 0; i < DIM / 4; i++) {
        float4 v = xr[i];
        s += v.x * v.x + v.y * v.y + v.z * v.z + v.w * v.w;
    }
    g_x2[row] = s;
}

__global__ void w2_kernel(const float* __restrict__ w, int K) {
    int j = blockIdx.x * blockDim.x + threadIdx.x;
    if (j >= K) return;
    float s = 0.0f;
#pragma unroll
    for (int d = 0; d < DIM; d++) {
        float v = w[(long)d * K + j];
        s += v * v;
    }
    g_w2[j] = s;
}

// ---------------------------------------------------------------------------
// tf32 helpers
// ---------------------------------------------------------------------------
__device__ __forceinline__ uint32_t f2tf32(float f) {
    uint32_t r;
    asm("cvt.rna.tf32.f32 %0, %1;" : "=r"(r) : "f"(f));
    return r;
}

__device__ __forceinline__ void mma_tf32(float c[4], const uint32_t a[4],
                                         const uint32_t b[2]) {
    asm volatile(
        "mma.sync.aligned.m16n8k8.row.col.f32.tf32.tf32.f32 "
        "{%0,%1,%2,%3}, {%4,%5,%6,%7}, {%8,%9}, {%0,%1,%2,%3};"
        : "+f"(c[0]), "+f"(c[1]), "+f"(c[2]), "+f"(c[3])
        : "r"(a[0]), "r"(a[1]), "r"(a[2]), "r"(a[3]), "r"(b[0]), "r"(b[1]));
}

// ---------------------------------------------------------------------------
// Fused distance GEMM via mma.sync tf32.
// CTA: 128x128 tile, 256 threads = 8 warps (2m x 4n), warp tile 64x32.
// SMEM: A[128][68] (pad 4), B[64][136] (pad 8), both tf32-rounded bits.
//   out[b,j] = sqrt(max(x2[b] + w2[j] - 2*dot, 1e-12))
// ---------------------------------------------------------------------------
#define A_STRIDE 68
#define B_STRIDE 136
#define SM_X2_OFF 0
#define SM_W2_OFF 128
#define SM_A_OFF  256
#define SM_B_OFF  (256 + 128 * A_STRIDE)          // 8960
#define SM_WORDS  (SM_B_OFF + 64 * B_STRIDE)      // 17664 words = 70656 B

__global__ __launch_bounds__(256, 2) void dist_mma_kernel(
    const float* __restrict__ x, const float* __restrict__ w,
    float* __restrict__ out, int B, int K)
{
    extern __shared__ uint32_t smem[];
    float* x2s = reinterpret_cast<float*>(smem + SM_X2_OFF);
    float* w2s = reinterpret_cast<float*>(smem + SM_W2_OFF);
    uint32_t* As = smem + SM_A_OFF;
    uint32_t* Bs = smem + SM_B_OFF;

    const int tid = threadIdx.x;
    const int lane = tid & 31;
    const int wid = tid >> 5;
    const int warp_m = wid >> 2;      // 0..1
    const int warp_n = wid & 3;       // 0..3
    const int m0 = blockIdx.y * TM;
    const int j0 = blockIdx.x * TN;

    // ---- squared norms into smem ----
    if (tid < 128) {
        x2s[tid] = g_x2[m0 + tid];
    } else {
        int j = j0 + tid - 128;
        w2s[tid - 128] = (j < K) ? g_w2[j] : 0.0f;
    }

    // ---- A tile: x[m0+r][d], 128x64, tf32-rounded, stride 68 ----
    {
        const float4* xs = reinterpret_cast<const float4*>(x + (long)m0 * DIM);
#pragma unroll
        for (int i = 0; i < 8; i++) {
            int e = tid + i * 256;       // float4 index, 0..2047
            int r = e >> 4;              // 16 float4 per row
            int c4 = e & 15;
            float4 v = xs[e];
            uint4 u = make_uint4(f2tf32(v.x), f2tf32(v.y), f2tf32(v.z), f2tf32(v.w));
            *reinterpret_cast<uint4*>(&As[r * A_STRIDE + c4 * 4]) = u;
        }
    }

    // ---- B tile: w[d][j0..j0+127], 64x128, tf32-rounded, stride 136 ----
    {
#pragma unroll
        for (int i = 0; i < 8; i++) {
            int e = tid + i * 256;       // float4 index, 0..2047
            int d = e >> 5;              // 32 float4 per row
            int c4 = e & 31;
            int j = j0 + c4 * 4;
            const float* wrow = w + (long)d * K;
            float4 v;
            if (j + 4 <= K) {
                v = *reinterpret_cast<const float4*>(wrow + j);
            } else {
                v.x = (j + 0 < K) ? wrow[j + 0] : 0.0f;
                v.y = (j + 1 < K) ? wrow[j + 1] : 0.0f;
                v.z = (j + 2 < K) ? wrow[j + 2] : 0.0f;
                v.w = (j + 3 < K) ? wrow[j + 3] : 0.0f;
            }
            uint4 u = make_uint4(f2tf32(v.x), f2tf32(v.y), f2tf32(v.z), f2tf32(v.w));
            *reinterpret_cast<uint4*>(&Bs[d * B_STRIDE + c4 * 4]) = u;
        }
    }

    __syncthreads();

    // ---- MMA mainloop: warp tile 64x32 = 4 mt x 4 nt of m16n8, 8 k-steps ----
    float acc[4][4][4];
#pragma unroll
    for (int mt = 0; mt < 4; mt++)
#pragma unroll
        for (int nt = 0; nt < 4; nt++)
#pragma unroll
            for (int q = 0; q < 4; q++) acc[mt][nt][q] = 0.0f;

    const int g = lane >> 2;     // group 0..7
    const int t = lane & 3;      // thread-in-group 0..3

#pragma unroll
    for (int ks = 0; ks < 8; ks++) {
        const int k0 = ks * 8;

        uint32_t a[4][4];
#pragma unroll
        for (int mt = 0; mt < 4; mt++) {
            int R = warp_m * 64 + mt * 16 + g;
            a[mt][0] = As[R * A_STRIDE + k0 + t];
            a[mt][1] = As[(R + 8) * A_STRIDE + k0 + t];
            a[mt][2] = As[R * A_STRIDE + k0 + t + 4];
            a[mt][3] = As[(R + 8) * A_STRIDE + k0 + t + 4];
        }

        uint32_t b[4][2];
#pragma unroll
        for (int nt = 0; nt < 4; nt++) {
            int C = warp_n * 32 + nt * 8 + g;
            b[nt][0] = Bs[(k0 + t) * B_STRIDE + C];
            b[nt][1] = Bs[(k0 + t + 4) * B_STRIDE + C];
        }

#pragma unroll
        for (int mt = 0; mt < 4; mt++)
#pragma unroll
            for (int nt = 0; nt < 4; nt++)
                mma_tf32(acc[mt][nt], a[mt], b[nt]);
    }

    // ---- Epilogue: dist = sqrt(max(x2 + w2 - 2*dot, eps)), fused store ----
#pragma unroll
    for (int mt = 0; mt < 4; mt++) {
        int R = warp_m * 64 + mt * 16 + g;
        float x2a = x2s[R];
        float x2b = x2s[R + 8];
        long row0 = (long)(m0 + R) * K;
        long row1 = (long)(m0 + R + 8) * K;
#pragma unroll
        for (int nt = 0; nt < 4; nt++) {
            int C = warp_n * 32 + nt * 8 + t * 2;
            int j = j0 + C;
            float w2a = w2s[C];
            float w2b = w2s[C + 1];
            float d0 = sqrtf(fmaxf(x2a + w2a - 2.0f * acc[mt][nt][0], 1e-12f));
            float d1 = sqrtf(fmaxf(x2a + w2b - 2.0f * acc[mt][nt][1], 1e-12f));
            float d2 = sqrtf(fmaxf(x2b + w2a - 2.0f * acc[mt][nt][2], 1e-12f));
            float d3 = sqrtf(fmaxf(x2b + w2b - 2.0f * acc[mt][nt][3], 1e-12f));
            if (j + 2 <= K) {
                *reinterpret_cast<float2*>(out + row0 + j) = make_float2(d0, d1);
                *reinterpret_cast<float2*>(out + row1 + j) = make_float2(d2, d3);
            } else if (j < K) {
                out[row0 + j] = d0;
                out[row1 + j] = d2;
            }
        }
    }
}

// ---------------------------------------------------------------------------
// Launch
// ---------------------------------------------------------------------------
extern "C" void kernel_launch(void* const* d_in, const int* in_sizes, int n_in,
                              void* d_out, int out_size) {
    const float* x = (const float*)d_in[0];   // [B, 64]
    const float* w = (const float*)d_in[1];   // [64, K]
    float* out = (float*)d_out;               // [B, K]

    int B = in_sizes[0] / DIM;
    int K = in_sizes[1] / DIM;

    x2_kernel<<<(B + 255) / 256, 256>>>(x, B);
    w2_kernel<<<(K + 255) / 256, 256>>>(w, K);

    cudaFuncSetAttribute(dist_mma_kernel,
                         cudaFuncAttributeMaxDynamicSharedMemorySize,
                         SM_WORDS * 4);
    dim3 grid((K + TN - 1) / TN, (B + TM - 1) / TM);
    dist_mma_kernel<<<grid, 256, SM_WORDS * 4>>>(x, w, out, B, K);
}

// round 5
// speedup vs baseline: 3.0901x; 1.2118x over previous
#include <cuda_runtime.h>
#include <cuda_fp16.h>
#include <math.h>
#include <stdint.h>

#define DIM 64
#define TM 128
#define TN 128

// Scratch for precomputed squared norms (no dynamic allocation allowed).
__device__ float g_x2[8192];
__device__ float g_w2[65536];

// ---------------------------------------------------------------------------
// Precompute squared norms (exact fp32)
// ---------------------------------------------------------------------------
__global__ void x2_kernel(const float* __restrict__ x, int B) {
    int row = blockIdx.x * blockDim.x + threadIdx.x;
    if (row >= B) return;
    const float4* xr = reinterpret_cast<const float4*>(x + (long)row * DIM);
    float s = 0.0f;
#pragma unroll
    for (int i = 0; i < DIM / 4; i++) {
        float4 v = xr[i];
        s += v.x * v.x + v.y * v.y + v.z * v.z + v.w * v.w;
    }
    g_x2[row] = s;
}

__global__ void w2_kernel(const float* __restrict__ w, int K) {
    int j = blockIdx.x * blockDim.x + threadIdx.x;
    if (j >= K) return;
    float s = 0.0f;
#pragma unroll
    for (int d = 0; d < DIM; d++) {
        float v = w[(long)d * K + j];
        s += v * v;
    }
    g_w2[j] = s;
}

// ---------------------------------------------------------------------------
// fp16 helpers
// ---------------------------------------------------------------------------
__device__ __forceinline__ uint32_t packh2(float lo, float hi) {
    __half2 h = __floats2half2_rn(lo, hi);   // x = lo (low 16b), y = hi
    return *reinterpret_cast<uint32_t*>(&h);
}

__device__ __forceinline__ void mma_f16(float c[4], const uint32_t a[4],
                                        const uint32_t b[2]) {
    asm volatile(
        "mma.sync.aligned.m16n8k16.row.col.f32.f16.f16.f32 "
        "{%0,%1,%2,%3}, {%4,%5,%6,%7}, {%8,%9}, {%0,%1,%2,%3};"
        : "+f"(c[0]), "+f"(c[1]), "+f"(c[2]), "+f"(c[3])
        : "r"(a[0]), "r"(a[1]), "r"(a[2]), "r"(a[3]), "r"(b[0]), "r"(b[1]));
}

// ---------------------------------------------------------------------------
// Fused distance GEMM via mma.sync fp16 (f32 accumulate).
// CTA: 128x128 tile, 256 threads = 8 warps (2m x 4n), warp tile 64x32.
// SMEM tiles: f16 pairs (uint32 words), row stride 36 words (32 data + 4 pad).
// Fragment read address = 36*g + t words; (36g+t)%32 = (4g+t)%32 covers all 32
// banks exactly once over the warp -> conflict-free.
//   out[b,j] = sqrt(max(x2[b] + w2[j] - 2*dot, 1e-12))
// ---------------------------------------------------------------------------
#define T_STRIDE 36   // uint32 words per tile row (64 halfs data + padding)

__global__ __launch_bounds__(256, 2) void dist_mma_kernel(
    const float* __restrict__ x, const float* __restrict__ w,
    float* __restrict__ out, int B, int K)
{
    __shared__ float x2s[128];
    __shared__ float w2s[128];
    __shared__ uint32_t As[128 * T_STRIDE];   // A[m][k] f16 pairs
    __shared__ uint32_t Bs[128 * T_STRIDE];   // B[n][k] f16 pairs (w transposed)

    const int tid = threadIdx.x;
    const int lane = tid & 31;
    const int wid = tid >> 5;
    const int warp_m = wid >> 2;      // 0..1
    const int warp_n = wid & 3;       // 0..3
    const int m0 = blockIdx.y * TM;
    const int j0 = blockIdx.x * TN;

    // ---- squared norms into smem ----
    if (tid < 128) {
        x2s[tid] = g_x2[m0 + tid];
    } else {
        int j = j0 + tid - 128;
        w2s[tid - 128] = (j < K) ? g_w2[j] : 0.0f;
    }

    // ---- A tile: x[m0+r][0..63] fp32 -> f16 pairs, row stride 36 words ----
    {
        const float4* xs = reinterpret_cast<const float4*>(x + (long)m0 * DIM);
#pragma unroll
        for (int i = 0; i < 8; i++) {
            int e = tid + i * 256;       // float4 index, 0..2047
            int r = e >> 4;              // 16 float4 per 64-float row
            int c4 = e & 15;
            float4 v = xs[e];
            uint2 u = make_uint2(packh2(v.x, v.y), packh2(v.z, v.w));
            *reinterpret_cast<uint2*>(&As[r * T_STRIDE + c4 * 2]) = u;
        }
    }

    // ---- B tile (transposed): Bs[n][k] = w[k][j0+n], f16 pairs ----
    {
        int n = tid & 127;
        int kh = (tid >> 7) * 32;        // k half-base: 0 or 32
        int j = j0 + n;
        bool inb = (j < K);
        const float* wp = w + j;
#pragma unroll
        for (int i = 0; i < 16; i++) {
            int d0 = kh + 2 * i;
            float f0 = inb ? wp[(long)d0 * K] : 0.0f;
            float f1 = inb ? wp[(long)(d0 + 1) * K] : 0.0f;
            Bs[n * T_STRIDE + (kh >> 1) + i] = packh2(f0, f1);
        }
    }

    __syncthreads();

    // ---- MMA mainloop: warp tile 64x32 = 4mt x 4nt of m16n8k16, 4 k-steps ----
    float acc[4][4][4];
#pragma unroll
    for (int mt = 0; mt < 4; mt++)
#pragma unroll
        for (int nt = 0; nt < 4; nt++)
#pragma unroll
            for (int q = 0; q < 4; q++) acc[mt][nt][q] = 0.0f;

    const int g = lane >> 2;     // group 0..7
    const int t = lane & 3;      // thread-in-group 0..3

#pragma unroll
    for (int ks = 0; ks < 4; ks++) {
        const int kw = ks * 8;   // k word base (16 halfs per step = 8 words)

        uint32_t a[4][4];
#pragma unroll
        for (int mt = 0; mt < 4; mt++) {
            int R = warp_m * 64 + mt * 16 + g;
            a[mt][0] = As[R * T_STRIDE + kw + t];
            a[mt][1] = As[(R + 8) * T_STRIDE + kw + t];
            a[mt][2] = As[R * T_STRIDE + kw + t + 4];
            a[mt][3] = As[(R + 8) * T_STRIDE + kw + t + 4];
        }

        uint32_t b[4][2];
#pragma unroll
        for (int nt = 0; nt < 4; nt++) {
            int C = warp_n * 32 + nt * 8 + g;
            b[nt][0] = Bs[C * T_STRIDE + kw + t];
            b[nt][1] = Bs[C * T_STRIDE + kw + t + 4];
        }

#pragma unroll
        for (int mt = 0; mt < 4; mt++)
#pragma unroll
            for (int nt = 0; nt < 4; nt++)
                mma_f16(acc[mt][nt], a[mt], b[nt]);
    }

    // ---- Epilogue: dist = sqrt(max(x2 + w2 - 2*dot, eps)), fused store ----
#pragma unroll
    for (int mt = 0; mt < 4; mt++) {
        int R = warp_m * 64 + mt * 16 + g;
        float x2a = x2s[R];
        float x2b = x2s[R + 8];
        long row0 = (long)(m0 + R) * K;
        long row1 = (long)(m0 + R + 8) * K;
#pragma unroll
        for (int nt = 0; nt < 4; nt++) {
            int C = warp_n * 32 + nt * 8 + t * 2;
            int j = j0 + C;
            float w2a = w2s[C];
            float w2b = w2s[C + 1];
            float d0 = sqrtf(fmaxf(x2a + w2a - 2.0f * acc[mt][nt][0], 1e-12f));
            float d1 = sqrtf(fmaxf(x2a + w2b - 2.0f * acc[mt][nt][1], 1e-12f));
            float d2 = sqrtf(fmaxf(x2b + w2a - 2.0f * acc[mt][nt][2], 1e-12f));
            float d3 = sqrtf(fmaxf(x2b + w2b - 2.0f * acc[mt][nt][3], 1e-12f));
            if (j + 2 <= K) {
                *reinterpret_cast<float2*>(out + row0 + j) = make_float2(d0, d1);
                *reinterpret_cast<float2*>(out + row1 + j) = make_float2(d2, d3);
            } else if (j < K) {
                out[row0 + j] = d0;
                out[row1 + j] = d2;
            }
        }
    }
}

// ---------------------------------------------------------------------------
// Launch
// ---------------------------------------------------------------------------
extern "C" void kernel_launch(void* const* d_in, const int* in_sizes, int n_in,
                              void* d_out, int out_size) {
    const float* x = (const float*)d_in[0];   // [B, 64]
    const float* w = (const float*)d_in[1];   // [64, K]
    float* out = (float*)d_out;               // [B, K]

    int B = in_sizes[0] / DIM;
    int K = in_sizes[1] / DIM;

    x2_kernel<<<(B + 255) / 256, 256>>>(x, B);
    w2_kernel<<<(K + 255) / 256, 256>>>(w, K);

    dim3 grid((K + TN - 1) / TN, (B + TM - 1) / TM);
    dist_mma_kernel<<<grid, 256>>>(x, w, out, B, K);
}